// round 5
// baseline (speedup 1.0000x reference)
#include <cuda_runtime.h>
#include <cstdint>
#include <cstddef>

#define DK  256
#define NB  32
#define NT  256
#define NHW 4096

// Scratch (static device globals; no allocation in kernel_launch)
__device__ float g_MT[DK * DK];      // MT[n][k] = sum_o Wq[o][k] * Wk[o][n]  ( = (Wq^T Wk)[k][n] )
__device__ float g_wv[DK];           // Wq^T bk
__device__ float g_wu[DK];           // Wk^T bq
__device__ float g_c;                // bq . bk
__device__ float g_G[NB * NT * DK];  // G = F_a @ (Wq^T Wk)
__device__ float g_v[NB * NT];       // v[t] = F_a[t] . g_wv
__device__ float g_psum[NB * NT * 32];

__device__ __forceinline__ uint32_t f2tf32(float f) {
    uint32_t u;
    asm("cvt.rna.tf32.f32 %0, %1;" : "=r"(u) : "f"(f));
    return u;
}

// ---------------------------------------------------------------------------
// prep_mt: MT[n][k] = sum_o Wq[o][k]*Wk[o][n]
// grid (16,16), block (16,16)
__global__ void prep_mt(const float* __restrict__ Wq, const float* __restrict__ Wk) {
    __shared__ float sq[16][17], sk2[16][17];
    int k0 = blockIdx.x * 16, n0 = blockIdx.y * 16;
    int tx = threadIdx.x, ty = threadIdx.y;
    float a = 0.f;
    for (int o0 = 0; o0 < DK; o0 += 16) {
        sq[ty][tx]  = Wq[(o0 + ty) * DK + k0 + tx];
        sk2[ty][tx] = Wk[(o0 + ty) * DK + n0 + tx];
        __syncthreads();
#pragma unroll
        for (int o = 0; o < 16; o++) a += sq[o][tx] * sk2[o][ty];
        __syncthreads();
    }
    g_MT[(n0 + ty) * DK + (k0 + tx)] = a;
}

// prep_vec: block k in [0,256): g_wv[k], g_wu[k]; block 0 also g_c.
__global__ void prep_vec(const float* __restrict__ Wq, const float* __restrict__ Wk,
                         const float* __restrict__ bq, const float* __restrict__ bk) {
    __shared__ float r1[256], r2[256], r3[256];
    int k = blockIdx.x, o = threadIdx.x;
    r1[o] = Wq[o * DK + k] * bk[o];
    r2[o] = Wk[o * DK + k] * bq[o];
    r3[o] = (k == 0) ? bq[o] * bk[o] : 0.f;
    __syncthreads();
    for (int s = 128; s > 0; s >>= 1) {
        if (o < s) { r1[o] += r1[o + s]; r2[o] += r2[o + s]; r3[o] += r3[o + s]; }
        __syncthreads();
    }
    if (o == 0) {
        g_wv[k] = r1[0];
        g_wu[k] = r2[0];
        if (k == 0) g_c = r3[0];
    }
}

// ---------------------------------------------------------------------------
// Shared tf32 mma.sync GEMM:
//   MODE 0: G = F_a @ MT^T-layout   (A=F_a [8192,256], B rows = MT[n][:]), also v-fold.
//   MODE 1: fused scores: E = exp((G@F_s^T + u + v + c)/16)*mask -> d_out, + psum partials.
// Tiles: M=64, N=128, K-slice=32.  8 warps as 2(m) x 4(n), each warp 32x32.
template <int MODE>
__global__ void __launch_bounds__(256, 2) gemm_kernel(
    const float* __restrict__ Aglob,   // MODE0: F_a
    const float* __restrict__ Bglob,   // MODE1: F_s
    const int*   __restrict__ Mask,    // MODE1: M_s flattened [B][HW]
    float*       __restrict__ Out)     // MODE1: d_out
{
    __shared__ float sA[64][36];
    __shared__ float sB[128][36];
    __shared__ float s_w[DK];
    __shared__ float s_u[128];
    __shared__ float s_vc[64];
    __shared__ float s_mask[128];
    __shared__ float s_ps[64][4];

    const int tid = threadIdx.x;
    const int s0 = blockIdx.x * 128;
    const int t0 = blockIdx.y * 64;
    const int b  = (MODE == 1) ? blockIdx.z : 0;

    const float* Abase;
    const float* Bbase;
    if (MODE == 0) {
        Abase = Aglob + (size_t)t0 * DK;
        Bbase = g_MT + (size_t)s0 * DK;
    } else {
        Abase = g_G + ((size_t)(b * NT + t0)) * DK;
        Bbase = Bglob + ((size_t)b * NHW + s0) * DK;
    }

    s_w[tid] = (MODE == 0) ? g_wv[tid] : g_wu[tid];
    if (MODE == 1 && tid < 128)
        s_mask[tid] = (Mask[(size_t)b * NHW + s0 + tid] != 0) ? 1.0f : 0.0f;

    const int warp = tid >> 5, lane = tid & 31;
    const int wm = warp >> 2, wn = warp & 3;
    const int g = lane >> 2, tg = lane & 3;

    float acc[2][4][4];
#pragma unroll
    for (int i = 0; i < 2; i++)
#pragma unroll
        for (int j = 0; j < 4; j++)
#pragma unroll
            for (int l = 0; l < 4; l++) acc[i][j][l] = 0.f;

    float fold = 0.f;  // MODE1: u[s] partial (tid<128); MODE0: v[t] partial (tid<64)

    const int arow = tid >> 2, acg = (tid & 3) * 8;
    const int brow = tid >> 1, bcg = (tid & 1) * 16;

    for (int kk0 = 0; kk0 < DK; kk0 += 32) {
        __syncthreads();
        // stage A slice 64x32 (tf32-rounded)
        {
            const float* src = Abase + (size_t)arow * DK + kk0 + acg;
            float4 v0 = *(const float4*)(src);
            float4 v1 = *(const float4*)(src + 4);
            sA[arow][acg + 0] = __uint_as_float(f2tf32(v0.x));
            sA[arow][acg + 1] = __uint_as_float(f2tf32(v0.y));
            sA[arow][acg + 2] = __uint_as_float(f2tf32(v0.z));
            sA[arow][acg + 3] = __uint_as_float(f2tf32(v0.w));
            sA[arow][acg + 4] = __uint_as_float(f2tf32(v1.x));
            sA[arow][acg + 5] = __uint_as_float(f2tf32(v1.y));
            sA[arow][acg + 6] = __uint_as_float(f2tf32(v1.z));
            sA[arow][acg + 7] = __uint_as_float(f2tf32(v1.w));
        }
        // stage B slice 128x32 (tf32-rounded)
        {
            const float* src = Bbase + (size_t)brow * DK + kk0 + bcg;
#pragma unroll
            for (int j = 0; j < 4; j++) {
                float4 v = *(const float4*)(src + 4 * j);
                sB[brow][bcg + 4 * j + 0] = __uint_as_float(f2tf32(v.x));
                sB[brow][bcg + 4 * j + 1] = __uint_as_float(f2tf32(v.y));
                sB[brow][bcg + 4 * j + 2] = __uint_as_float(f2tf32(v.z));
                sB[brow][bcg + 4 * j + 3] = __uint_as_float(f2tf32(v.w));
            }
        }
        __syncthreads();

        // bias folds (u from staged F_s, v from staged F_a)
        if (MODE == 1) {
            if (tid < 128) {
                float a = 0.f;
#pragma unroll
                for (int k = 0; k < 32; k++) a += sB[tid][k] * s_w[kk0 + k];
                fold += a;
            }
        } else {
            if (blockIdx.x == 0 && tid < 64) {
                float a = 0.f;
#pragma unroll
                for (int k = 0; k < 32; k++) a += sA[tid][k] * s_w[kk0 + k];
                fold += a;
            }
        }

        // mma over this k-slice: 4 x k8 steps
#pragma unroll
        for (int kk = 0; kk < 32; kk += 8) {
            uint32_t af[2][4];
            uint32_t bf[4][2];
#pragma unroll
            for (int mt = 0; mt < 2; mt++) {
                int r = wm * 32 + mt * 16;
                af[mt][0] = __float_as_uint(sA[r + g    ][kk + tg    ]);
                af[mt][1] = __float_as_uint(sA[r + g + 8][kk + tg    ]);
                af[mt][2] = __float_as_uint(sA[r + g    ][kk + tg + 4]);
                af[mt][3] = __float_as_uint(sA[r + g + 8][kk + tg + 4]);
            }
#pragma unroll
            for (int nt = 0; nt < 4; nt++) {
                int cb = wn * 32 + nt * 8;
                bf[nt][0] = __float_as_uint(sB[cb + g][kk + tg    ]);
                bf[nt][1] = __float_as_uint(sB[cb + g][kk + tg + 4]);
            }
#pragma unroll
            for (int mt = 0; mt < 2; mt++)
#pragma unroll
                for (int nt = 0; nt < 4; nt++) {
                    asm volatile(
                        "mma.sync.aligned.m16n8k8.row.col.f32.tf32.tf32.f32 "
                        "{%0,%1,%2,%3}, {%4,%5,%6,%7}, {%8,%9}, {%0,%1,%2,%3};"
                        : "+f"(acc[mt][nt][0]), "+f"(acc[mt][nt][1]),
                          "+f"(acc[mt][nt][2]), "+f"(acc[mt][nt][3])
                        : "r"(af[mt][0]), "r"(af[mt][1]), "r"(af[mt][2]), "r"(af[mt][3]),
                          "r"(bf[nt][0]), "r"(bf[nt][1]));
                }
        }
    }

    if (MODE == 0) {
        if (blockIdx.x == 0 && tid < 64) g_v[t0 + tid] = fold;
#pragma unroll
        for (int mt = 0; mt < 2; mt++)
#pragma unroll
            for (int nt = 0; nt < 4; nt++) {
                int r0 = t0 + wm * 32 + mt * 16 + g;
                int c  = s0 + wn * 32 + nt * 8 + 2 * tg;
                float* o0 = g_G + (size_t)r0 * DK + c;
                *(float2*)o0 = make_float2(acc[mt][nt][0], acc[mt][nt][1]);
                *(float2*)(o0 + (size_t)8 * DK) = make_float2(acc[mt][nt][2], acc[mt][nt][3]);
            }
    } else {
        if (tid < 128) s_u[tid] = fold;
        if (tid < 64)  s_vc[tid] = g_v[b * NT + t0 + tid] + g_c;
        __syncthreads();

#pragma unroll
        for (int mt = 0; mt < 2; mt++) {
            int rl0 = wm * 32 + mt * 16 + g;
            int rl1 = rl0 + 8;
            float rp0 = 0.f, rp1 = 0.f;
#pragma unroll
            for (int nt = 0; nt < 4; nt++) {
                int c = wn * 32 + nt * 8 + 2 * tg;
                float u0 = s_u[c], u1 = s_u[c + 1];
                float m0 = s_mask[c], m1 = s_mask[c + 1];
                float v0 = s_vc[rl0], v1 = s_vc[rl1];
                float e00 = m0 * __expf((acc[mt][nt][0] + u0 + v0) * 0.0625f);
                float e01 = m1 * __expf((acc[mt][nt][1] + u1 + v0) * 0.0625f);
                float e10 = m0 * __expf((acc[mt][nt][2] + u0 + v1) * 0.0625f);
                float e11 = m1 * __expf((acc[mt][nt][3] + u1 + v1) * 0.0625f);
                size_t base0 = ((size_t)(b * NT + t0 + rl0)) * NHW + s0 + c;
                size_t base1 = ((size_t)(b * NT + t0 + rl1)) * NHW + s0 + c;
                *(float2*)(Out + base0) = make_float2(e00, e01);
                *(float2*)(Out + base1) = make_float2(e10, e11);
                rp0 += e00 + e01;
                rp1 += e10 + e11;
            }
            rp0 += __shfl_xor_sync(0xffffffffu, rp0, 1);
            rp0 += __shfl_xor_sync(0xffffffffu, rp0, 2);
            rp1 += __shfl_xor_sync(0xffffffffu, rp1, 1);
            rp1 += __shfl_xor_sync(0xffffffffu, rp1, 2);
            if (tg == 0) { s_ps[rl0][wn] = rp0; s_ps[rl1][wn] = rp1; }
        }
        __syncthreads();
        if (tid < 64) {
            g_psum[((size_t)(b * NT + t0 + tid)) * 32 + blockIdx.x] =
                (s_ps[tid][0] + s_ps[tid][1]) + (s_ps[tid][2] + s_ps[tid][3]);
        }
    }
}

// ---------------------------------------------------------------------------
// scale: out[row,:] *= 1 / sum(partials[row])
__global__ void __launch_bounds__(256) scale_kernel(float* __restrict__ out) {
    int row = blockIdx.x;
    __shared__ float sinv;
    if (threadIdx.x < 32) {
        float p = g_psum[(size_t)row * 32 + threadIdx.x];
#pragma unroll
        for (int o = 16; o; o >>= 1) p += __shfl_xor_sync(0xffffffffu, p, o);
        if (threadIdx.x == 0) sinv = 1.0f / p;
    }
    __syncthreads();
    float inv = sinv;
    float4* o4 = (float4*)(out + (size_t)row * NHW);
#pragma unroll
    for (int i = 0; i < 4; i++) {
        int idx = threadIdx.x + i * 256;
        float4 v = o4[idx];
        v.x *= inv; v.y *= inv; v.z *= inv; v.w *= inv;
        o4[idx] = v;
    }
}

// ---------------------------------------------------------------------------
extern "C" void kernel_launch(void* const* d_in, const int* in_sizes, int n_in,
                              void* d_out, int out_size) {
    (void)in_sizes; (void)n_in; (void)out_size;
    const float* F_a = (const float*)d_in[0];
    const float* F_s = (const float*)d_in[1];
    const int*   M_s = (const int*)  d_in[2];
    const float* Wq  = (const float*)d_in[3];
    const float* bq  = (const float*)d_in[4];
    const float* Wk  = (const float*)d_in[5];
    const float* bk  = (const float*)d_in[6];
    float* out = (float*)d_out;

    prep_mt<<<dim3(16, 16), dim3(16, 16)>>>(Wq, Wk);
    prep_vec<<<DK, 256>>>(Wq, Wk, bq, bk);
    gemm_kernel<0><<<dim3(2, 128, 1), 256>>>(F_a, nullptr, nullptr, nullptr);
    gemm_kernel<1><<<dim3(32, 4, 32), 256>>>(nullptr, F_s, M_s, out);
    scale_kernel<<<NB * NT, 256>>>(out);
}